// round 2
// baseline (speedup 1.0000x reference)
#include <cuda_runtime.h>
#include <cstdint>

#define Bz 8
#define Nn 10000
#define Ee 160000
#define Hh 128
#define Zz 64

// ---------------- static device scratch (no allocations allowed) ----------------
__device__ int   g_deg[Nn];
__device__ int   g_rowptr[Nn + 1];
__device__ int   g_cursor[Nn];
__device__ int   g_csr[Ee];
__device__ float g_agg1[Bz * Nn];
__device__ float g_h1[Bz * Nn * Hh];   // 40.96 MB
__device__ float g_S[Bz * Nn * Hh];    // 40.96 MB (layer-2 mean-aggregated features)
__device__ float g_WT[2 * Hh * Hh];    // [d][h]: d<128 -> W2l[h][d], d>=128 -> W2r[h][d-128]
__device__ float g_pool[Bz * Hh];      // accumulated column sums of h2

// ---------------- kernels ----------------

__global__ void k_init() {
    int i = blockIdx.x * blockDim.x + threadIdx.x;
    if (i < Nn)      g_deg[i] = 0;
    if (i < Bz * Nn) g_agg1[i] = 0.f;
    if (i < Bz * Hh) g_pool[i] = 0.f;
}

// degree histogram + layer-1 scalar aggregation (all 8 batches per edge)
// NOTE: edge_index is int32 (JAX x64 disabled downcasts jnp.int64 silently).
__global__ void k_deg_agg(const int* __restrict__ ei, const float* __restrict__ x) {
    int e = blockIdx.x * blockDim.x + threadIdx.x;
    if (e >= Ee) return;
    int s = ei[e];
    int d = ei[Ee + e];
    atomicAdd(&g_deg[d], 1);
#pragma unroll
    for (int b = 0; b < Bz; b++)
        atomicAdd(&g_agg1[b * Nn + d], __ldg(&x[b * Nn + s]));
}

// exclusive prefix sum over g_deg -> g_rowptr, copy to g_cursor. One block of 1024.
__global__ void k_scan() {
    __shared__ int sdata[1024];
    const int t = threadIdx.x;
    const int base = t * 10;
    int vals[10];
    int sum = 0;
#pragma unroll
    for (int i = 0; i < 10; i++) {
        int idx = base + i;
        int d = (idx < Nn) ? g_deg[idx] : 0;
        vals[i] = sum;     // thread-local exclusive
        sum += d;
    }
    sdata[t] = sum;
    __syncthreads();
    // Hillis-Steele inclusive scan over 1024 partials
    for (int off = 1; off < 1024; off <<= 1) {
        int v = (t >= off) ? sdata[t - off] : 0;
        __syncthreads();
        sdata[t] += v;
        __syncthreads();
    }
    int blockoff = (t > 0) ? sdata[t - 1] : 0;
#pragma unroll
    for (int i = 0; i < 10; i++) {
        int idx = base + i;
        if (idx < Nn) {
            int v = blockoff + vals[i];
            g_rowptr[idx] = v;
            g_cursor[idx] = v;
        }
    }
    if (t == 1023) g_rowptr[Nn] = sdata[1023];
}

__global__ void k_scatter(const int* __restrict__ ei) {
    int e = blockIdx.x * blockDim.x + threadIdx.x;
    if (e >= Ee) return;
    int s = ei[e];
    int d = ei[Ee + e];
    int pos = atomicAdd(&g_cursor[d], 1);
    g_csr[pos] = s;
}

// h1[b,n,h] = relu(W1l[h]*agg1 + W1r[h]*x + b1[h]); one thread per 4 h (float4)
__global__ void k_h1(const float* __restrict__ x, const float* __restrict__ W1l,
                     const float* __restrict__ b1, const float* __restrict__ W1r) {
    int gid = blockIdx.x * blockDim.x + threadIdx.x;
    if (gid >= Bz * Nn * (Hh / 4)) return;
    int h4 = gid & 31;          // 0..31 (group of 4 h)
    int row = gid >> 5;         // 0..79999  (b*Nn + n)
    int n = row % Nn;
    float a = g_agg1[row] / fmaxf((float)g_deg[n], 1.f);
    float xv = __ldg(&x[row]);
    float4 wl = __ldg(((const float4*)W1l) + h4);
    float4 wr = __ldg(((const float4*)W1r) + h4);
    float4 bb = __ldg(((const float4*)b1) + h4);
    float4 o;
    o.x = fmaxf(wl.x * a + wr.x * xv + bb.x, 0.f);
    o.y = fmaxf(wl.y * a + wr.y * xv + bb.y, 0.f);
    o.z = fmaxf(wl.z * a + wr.z * xv + bb.z, 0.f);
    o.w = fmaxf(wl.w * a + wr.w * xv + bb.w, 0.f);
    *((float4*)&g_h1[(size_t)row * Hh + h4 * 4]) = o;
}

// transpose + concat weights: WT[d*H + h]
__global__ void k_wt(const float* __restrict__ W2l, const float* __restrict__ W2r) {
    int i = blockIdx.x * blockDim.x + threadIdx.x;
    if (i >= 2 * Hh * Hh) return;
    int h = i % Hh;
    int d = i / Hh;
    g_WT[i] = (d < Hh) ? __ldg(&W2l[h * Hh + d]) : __ldg(&W2r[h * Hh + (d - Hh)]);
}

// warp per (b,node): CSR gather of h1 rows (512B each, L2-resident per batch), mean -> g_S
__global__ void k_agg2() {
    int unit = (blockIdx.x * blockDim.x + threadIdx.x) >> 5;
    int lane = threadIdx.x & 31;
    if (unit >= Bz * Nn) return;
    int b = unit / Nn;
    int n = unit - b * Nn;
    int beg = g_rowptr[n];
    int end = g_rowptr[n + 1];
    const float* hb = g_h1 + (size_t)b * Nn * Hh;
    float4 acc = make_float4(0.f, 0.f, 0.f, 0.f);
    for (int e = beg; e < end; e++) {
        int s = g_csr[e];
        float4 v = *((const float4*)&hb[(size_t)s * Hh + lane * 4]);
        acc.x += v.x; acc.y += v.y; acc.z += v.z; acc.w += v.w;
    }
    float inv = 1.f / fmaxf((float)(end - beg), 1.f);
    acc.x *= inv; acc.y *= inv; acc.z *= inv; acc.w *= inv;
    *((float4*)&g_S[(size_t)unit * Hh + lane * 4]) = acc;
}

// GEMM: z[row, h] = relu( [S_row | h1_row] (256) . WT[:, h] + b2[h] ), pooled += z
// tile: 64 rows x 128 cols x K-chunks of 16; 256 threads, each 8x4 outputs.
#define NTILE 157
__global__ void __launch_bounds__(256, 4) k_gemm(const float* __restrict__ b2) {
    __shared__ float As[16][65];    // [k][row], padded
    __shared__ float Ws[16][128];   // [k][h]
    __shared__ float red[8][128];

    const int b = blockIdx.y;
    const int row0 = blockIdx.x * 64;
    const int t = threadIdx.x;
    const int tx = t & 31;          // col group: cols tx*4..tx*4+3
    const int ty = t >> 5;          // row group: rows ty*8..ty*8+7

    const size_t rowbase = (size_t)b * Nn * Hh;

    float acc[8][4];
#pragma unroll
    for (int i = 0; i < 8; i++)
#pragma unroll
        for (int j = 0; j < 4; j++) acc[i][j] = 0.f;

    const int lr = t >> 2;   // A-load row within tile (0..63)
    const int lk = t & 3;    // A-load k-quad (0..3)

    for (int chunk = 0; chunk < 16; chunk++) {
        const float* Abuf = (chunk < 8) ? g_S : g_h1;
        const int dbase = (chunk < 8) ? chunk * 16 : (chunk - 8) * 16;

        // load A tile (64 x 16), transposed into As[k][row]
        float4 av = make_float4(0.f, 0.f, 0.f, 0.f);
        int row = row0 + lr;
        if (row < Nn)
            av = *((const float4*)&Abuf[rowbase + (size_t)row * Hh + dbase + lk * 4]);
        As[lk * 4 + 0][lr] = av.x;
        As[lk * 4 + 1][lr] = av.y;
        As[lk * 4 + 2][lr] = av.z;
        As[lk * 4 + 3][lr] = av.w;

        // load W tile (16 x 128), coalesced from pre-transposed WT
#pragma unroll
        for (int q = 0; q < 2; q++) {
            int fi = q * 256 + t;          // 0..511 float4s
            int k = fi >> 5;
            int h4 = fi & 31;
            *((float4*)&Ws[k][h4 * 4]) =
                *((const float4*)&g_WT[(size_t)(chunk * 16 + k) * Hh + h4 * 4]);
        }
        __syncthreads();

#pragma unroll
        for (int k = 0; k < 16; k++) {
            float4 w = *((const float4*)&Ws[k][tx * 4]);
#pragma unroll
            for (int i = 0; i < 8; i++) {
                float a = As[k][ty * 8 + i];
                acc[i][0] += a * w.x;
                acc[i][1] += a * w.y;
                acc[i][2] += a * w.z;
                acc[i][3] += a * w.w;
            }
        }
        __syncthreads();
    }

    // epilogue: +b2, relu, column sums over valid rows
    float4 bb = __ldg(((const float4*)b2) + tx);
    float csum[4] = {0.f, 0.f, 0.f, 0.f};
#pragma unroll
    for (int i = 0; i < 8; i++) {
        int row = row0 + ty * 8 + i;
        if (row < Nn) {
            csum[0] += fmaxf(acc[i][0] + bb.x, 0.f);
            csum[1] += fmaxf(acc[i][1] + bb.y, 0.f);
            csum[2] += fmaxf(acc[i][2] + bb.z, 0.f);
            csum[3] += fmaxf(acc[i][3] + bb.w, 0.f);
        }
    }
#pragma unroll
    for (int j = 0; j < 4; j++) red[ty][tx * 4 + j] = csum[j];
    __syncthreads();
    if (t < 128) {
        float s = 0.f;
#pragma unroll
        for (int r = 0; r < 8; r++) s += red[r][t];
        atomicAdd(&g_pool[b * Hh + t], s);
    }
}

// final MLP: pooled mean -> relu(Wro1) -> Wro2 -> out (8 x 64)
__global__ void k_final(float* __restrict__ out,
                        const float* __restrict__ Wro1, const float* __restrict__ bro1,
                        const float* __restrict__ Wro2, const float* __restrict__ bro2) {
    __shared__ float pl[Bz][Hh];
    __shared__ float hid[Bz][Hh];
    int t = threadIdx.x;  // 128
    const float invn = 1.f / (float)Nn;
#pragma unroll
    for (int b = 0; b < Bz; b++) pl[b][t] = g_pool[b * Hh + t] * invn;
    __syncthreads();
#pragma unroll
    for (int b = 0; b < Bz; b++) {
        float s = __ldg(&bro1[t]);
        for (int h = 0; h < Hh; h++) s += pl[b][h] * __ldg(&Wro1[t * Hh + h]);
        hid[b][t] = fmaxf(s, 0.f);
    }
    __syncthreads();
    if (t < Zz) {
#pragma unroll
        for (int b = 0; b < Bz; b++) {
            float s = __ldg(&bro2[t]);
            for (int h = 0; h < Hh; h++) s += hid[b][h] * __ldg(&Wro2[t * Hh + h]);
            out[b * Zz + t] = s;
        }
    }
}

// ---------------- launcher ----------------
extern "C" void kernel_launch(void* const* d_in, const int* in_sizes, int n_in,
                              void* d_out, int out_size) {
    const float* x    = (const float*)d_in[0];
    const int*   ei   = (const int*)d_in[1];     // int32! (JAX x64 disabled)
    const float* W1l  = (const float*)d_in[2];
    const float* b1   = (const float*)d_in[3];
    const float* W1r  = (const float*)d_in[4];
    const float* W2l  = (const float*)d_in[5];
    const float* b2   = (const float*)d_in[6];
    const float* W2r  = (const float*)d_in[7];
    const float* Wro1 = (const float*)d_in[8];
    const float* bro1 = (const float*)d_in[9];
    const float* Wro2 = (const float*)d_in[10];
    const float* bro2 = (const float*)d_in[11];
    float* out = (float*)d_out;

    k_init<<<(Bz * Nn + 255) / 256, 256>>>();
    k_deg_agg<<<(Ee + 255) / 256, 256>>>(ei, x);
    k_scan<<<1, 1024>>>();
    k_scatter<<<(Ee + 255) / 256, 256>>>(ei);
    k_h1<<<(Bz * Nn * (Hh / 4) + 255) / 256, 256>>>(x, W1l, b1, W1r);
    k_wt<<<(2 * Hh * Hh + 255) / 256, 256>>>(W2l, W2r);
    k_agg2<<<(Bz * Nn * 32 + 255) / 256, 256>>>();
    k_gemm<<<dim3(NTILE, Bz), 256>>>(b2);
    k_final<<<1, 128>>>(out, Wro1, bro1, Wro2, bro2);
}